// round 16
// baseline (speedup 1.0000x reference)
#include <cuda_runtime.h>
#include <cuda_fp16.h>
#include <math.h>
#include <stdint.h>

// Problem constants
#define B_    2
#define S_    2048
#define H_    2048
#define NH    32
#define NKV   8
#define HD    64
#define KVD   512           // NKV * HD
#define QKVD  3072          // H_ + 2*KVD
#define MROWS 4096          // B_ * S_

// fp16 packed QKV projection output (q | k | v columns)
__device__ __half g_qkv16[MROWS * QKVD];
__device__ float2 g_cs[S_ * 32];

// fp16 operands
__device__ __half g_xh   [MROWS * H_];
__device__ __half g_wqkv [QKVD * H_];       // wq | wk | wv packed rows
__device__ __half g_woh  [H_ * H_];
__device__ __half g_aoh  [MROWS * H_];
__device__ __half g_qh   [MROWS * H_];
__device__ __half g_kh   [MROWS * KVD];

// ---------------------------------------------------------------------------
// helpers
// ---------------------------------------------------------------------------
__device__ __forceinline__ void mma16816(float* c, const uint32_t* a, const uint32_t* b) {
    asm volatile(
        "mma.sync.aligned.m16n8k16.row.col.f32.f16.f16.f32 "
        "{%0,%1,%2,%3}, {%4,%5,%6,%7}, {%8,%9}, {%0,%1,%2,%3};\n"
        : "+f"(c[0]), "+f"(c[1]), "+f"(c[2]), "+f"(c[3])
        : "r"(a[0]), "r"(a[1]), "r"(a[2]), "r"(a[3]), "r"(b[0]), "r"(b[1]));
}
__device__ __forceinline__ void ldsm4(uint32_t* r, uint32_t addr) {
    asm volatile("ldmatrix.sync.aligned.m8n8.x4.shared.b16 {%0,%1,%2,%3}, [%4];\n"
                 : "=r"(r[0]), "=r"(r[1]), "=r"(r[2]), "=r"(r[3]) : "r"(addr));
}
__device__ __forceinline__ void ldsm4t(uint32_t* r, uint32_t addr) {
    asm volatile("ldmatrix.sync.aligned.m8n8.x4.trans.shared.b16 {%0,%1,%2,%3}, [%4];\n"
                 : "=r"(r[0]), "=r"(r[1]), "=r"(r[2]), "=r"(r[3]) : "r"(addr));
}
__device__ __forceinline__ uint32_t pack_h(float a, float b) {
    __half2 t = __floats2half2_rn(a, b);
    return *(uint32_t*)&t;
}
__device__ __forceinline__ void cp16(uint32_t dst, const void* src) {
    asm volatile("cp.async.cg.shared.global [%0], [%1], 16;\n" :: "r"(dst), "l"(src));
}

// ---------------------------------------------------------------------------
// Fused fp32 -> fp16 convert of x + all four weights (one launch)
// ---------------------------------------------------------------------------
#define CN0 (MROWS * H_ / 4)     // x
#define CN1 (H_ * H_ / 4)        // wq
#define CN2 (KVD * H_ / 4)       // wk
#define CN3 (KVD * H_ / 4)       // wv
#define CN4 (H_ * H_ / 4)        // wo
#define CNT (CN0 + CN1 + CN2 + CN3 + CN4)

__global__ void convert_all(const float* __restrict__ x,  const float* __restrict__ wq,
                            const float* __restrict__ wk, const float* __restrict__ wv,
                            const float* __restrict__ wo) {
    int c = blockIdx.x * blockDim.x + threadIdx.x;
    if (c >= CNT) return;
    const float* src;
    __half* dst;
    int i;
    if (c < CN0)                       { src = x;  dst = g_xh;   i = c; }
    else if (c < CN0 + CN1)            { src = wq; dst = g_wqkv; i = c - CN0; }
    else if (c < CN0 + CN1 + CN2)      { src = wk; dst = g_wqkv + (size_t)H_ * H_; i = c - CN0 - CN1; }
    else if (c < CN0 + CN1 + CN2 + CN3){ src = wv; dst = g_wqkv + (size_t)(H_ + KVD) * H_; i = c - CN0 - CN1 - CN2; }
    else                               { src = wo; dst = g_woh;  i = c - CN0 - CN1 - CN2 - CN3; }
    i *= 4;
    float4 v = *(const float4*)(src + i);
    *(__half2*)&dst[i]     = __floats2half2_rn(v.x, v.y);
    *(__half2*)&dst[i + 2] = __floats2half2_rn(v.z, v.w);
}

// ---------------------------------------------------------------------------
// Pipelined plain-fp16 GEMM: C[M,N] = A[M,K] @ B[N,K]^T
// 128x128 tile, BK=32, 3-stage cp.async, 256 threads, warp tile 64x32,
// 2 CTAs/SM. out_half selects fp16 or fp32 C.
// ---------------------------------------------------------------------------
#define ST 40                      // smem row stride (fp16 elems)
#define ABYTES (128 * ST * 2)      // 10240 per array
#define STAGEB (2 * ABYTES)        // A, B = 20480 per stage
#define SMEMSZ (3 * STAGEB)        // 61440

__global__ void __launch_bounds__(256, 2)
gemm_pre(const __half* __restrict__ A, const __half* __restrict__ B,
         void* __restrict__ Cv, int M, int N, int K, int out_half) {
    extern __shared__ char dsm[];
    const uint32_t smem0 = (uint32_t)__cvta_generic_to_shared(dsm);

    const int t    = threadIdx.x;
    const int lane = t & 31;
    const int w    = t >> 5;
    const int wm   = (w & 1) * 64;
    const int wn   = (w >> 1) * 32;
    const int m0   = blockIdx.y * 128;
    const int n0   = blockIdx.x * 128;

    const int g = lane >> 3, r = lane & 7;
    const int a_moff = (g & 1) * 8 + r;
    const int a_koff = (g >> 1) * 8;
    const int b_noff = (g >> 1) * 8 + r;
    const int b_koff = (g & 1) * 8;

    const int r0 = t >> 2, c0 = (t & 3) * 8;
    const int r1 = (t + 256) >> 2, c1 = ((t + 256) & 3) * 8;

    const int nkt = K >> 5;

    auto issue = [&](int kt) {
        int k0 = kt << 5;
        uint32_t base = smem0 + (kt % 3) * STAGEB;
        uint32_t d0 = base + (r0 * ST + c0) * 2;
        uint32_t d1 = base + (r1 * ST + c1) * 2;
        size_t ao0 = (size_t)(m0 + r0) * K + k0 + c0;
        size_t ao1 = (size_t)(m0 + r1) * K + k0 + c1;
        size_t bo0 = (size_t)(n0 + r0) * K + k0 + c0;
        size_t bo1 = (size_t)(n0 + r1) * K + k0 + c1;
        cp16(d0,          A + ao0); cp16(d1,          A + ao1);
        cp16(d0 + ABYTES, B + bo0); cp16(d1 + ABYTES, B + bo1);
    };

    float acc[4][4][4];
#pragma unroll
    for (int i = 0; i < 4; i++)
#pragma unroll
        for (int j = 0; j < 4; j++)
#pragma unroll
            for (int e = 0; e < 4; e++) acc[i][j][e] = 0.f;

    issue(0); asm volatile("cp.async.commit_group;\n");
    issue(1); asm volatile("cp.async.commit_group;\n");

    for (int kt = 0; kt < nkt; kt++) {
        asm volatile("cp.async.wait_group 1;\n");
        __syncthreads();
        if (kt + 2 < nkt) issue(kt + 2);
        asm volatile("cp.async.commit_group;\n");

        const uint32_t base = smem0 + (kt % 3) * STAGEB;
        const uint32_t sA = base, sB = base + ABYTES;

#pragma unroll
        for (int ks = 0; ks < 2; ks++) {
            const int kk = ks * 16;
            uint32_t af[4][4], bf[2][4];
#pragma unroll
            for (int mi = 0; mi < 4; mi++)
                ldsm4(af[mi], sA + 2u * ((wm + mi * 16 + a_moff) * ST + kk + a_koff));
#pragma unroll
            for (int nb = 0; nb < 2; nb++)
                ldsm4(bf[nb], sB + 2u * ((wn + nb * 16 + b_noff) * ST + kk + b_koff));
#pragma unroll
            for (int mi = 0; mi < 4; mi++)
#pragma unroll
                for (int ni = 0; ni < 4; ni++)
                    mma16816(acc[mi][ni], af[mi], &bf[ni >> 1][(ni & 1) * 2]);
        }
        __syncthreads();
    }

    if (out_half) {
        __half* C = (__half*)Cv;
#pragma unroll
        for (int mi = 0; mi < 4; mi++) {
            int row = m0 + wm + mi * 16 + (lane >> 2);
#pragma unroll
            for (int ni = 0; ni < 4; ni++) {
                int col = n0 + wn + ni * 8 + (lane & 3) * 2;
                *(__half2*)&C[(size_t)row * N + col]       = __floats2half2_rn(acc[mi][ni][0], acc[mi][ni][1]);
                *(__half2*)&C[(size_t)(row + 8) * N + col] = __floats2half2_rn(acc[mi][ni][2], acc[mi][ni][3]);
            }
        }
    } else {
        float* C = (float*)Cv;
#pragma unroll
        for (int mi = 0; mi < 4; mi++) {
            int row = m0 + wm + mi * 16 + (lane >> 2);
#pragma unroll
            for (int ni = 0; ni < 4; ni++) {
                int col = n0 + wn + ni * 8 + (lane & 3) * 2;
                *(float2*)&C[(size_t)row * N + col]       = make_float2(acc[mi][ni][0], acc[mi][ni][1]);
                *(float2*)&C[(size_t)(row + 8) * N + col] = make_float2(acc[mi][ni][2], acc[mi][ni][3]);
            }
        }
    }
}

// ---------------------------------------------------------------------------
// cos/sin table
// ---------------------------------------------------------------------------
__global__ void cs_table_kernel() {
    int i = blockIdx.x * blockDim.x + threadIdx.x;
    if (i >= S_ * 32) return;
    int pos = i >> 5, p = i & 31;
    double inv = exp(-((double)(2 * p) / 64.0) * log(10000.0));
    double ang = (double)pos * inv;
    g_cs[i] = make_float2((float)cos(ang), (float)sin(ang));
}

// ---------------------------------------------------------------------------
// RoPE on Q,K from fp16 packed qkv: 2 adjacent pairs per thread (half2 I/O).
// Q -> g_qh (stride H_), K -> g_kh (stride KVD). V stays in qkv16.
// ---------------------------------------------------------------------------
__global__ void rope16_kernel(const __half* __restrict__ qkv) {
    const int NQ2 = MROWS * 512;          // q: 1024 pairs/row, 2 per thread
    const int NK2 = MROWS * 128;          // k: 256 pairs/row, 2 per thread
    int idx = blockIdx.x * blockDim.x + threadIdx.x;
    if (idx >= NQ2 + NK2) return;

    const __half* srcp;
    __half* dstp;
    int row, head, pp;
    if (idx < NQ2) {
        row = idx >> 9; int rem = idx & 511;
        head = rem >> 4; pp = (rem & 15) * 2;
        srcp = qkv + (size_t)row * QKVD + head * HD;
        dstp = g_qh + (size_t)row * H_ + head * HD;
    } else {
        int i2 = idx - NQ2;
        row = i2 >> 7; int rem = i2 & 127;
        head = rem >> 4; pp = (rem & 15) * 2;
        srcp = qkv + (size_t)row * QKVD + H_ + head * HD;
        dstp = g_kh + (size_t)row * KVD + head * HD;
    }
    int pos = row & (S_ - 1);
    float2 csA = g_cs[pos * 32 + pp];
    float2 csB = g_cs[pos * 32 + pp + 1];
    __half2 v0 = *(const __half2*)(srcp + pp);        // x[pp], x[pp+1]
    __half2 v1 = *(const __half2*)(srcp + pp + 32);   // x[pp+32], x[pp+33]
    float a0 = __half2float(v0.x), a1 = __half2float(v0.y);
    float b0 = __half2float(v1.x), b1 = __half2float(v1.y);
    *(__half2*)(dstp + pp) = __floats2half2_rn(
        a0 * csA.x - b0 * csA.y, a1 * csB.x - b1 * csB.y);
    *(__half2*)(dstp + pp + 32) = __floats2half2_rn(
        b0 * csA.x + a0 * csA.y, b1 * csB.x + a1 * csB.y);
}

// ---------------------------------------------------------------------------
// Tensor-core causal flash attention: all single fp16 (1-pass QK, 1-pass PV).
// V read directly from packed qkv16 (row stride QKVD). 2-stage cp.async; LPT.
// ---------------------------------------------------------------------------
#define ST2 72
#define FA  (64 * ST2 * 2)
#define FSTAGE (2 * FA)             // K, V
#define FSMEM  (2 * FSTAGE)         // 36864

__global__ void __launch_bounds__(128)
flash2(const __half* __restrict__ Qh, const __half* __restrict__ Kh,
       const __half* __restrict__ Vh,          // = qkv16 + H_ + KVD, stride QKVD
       __half* __restrict__ AOh) {
    extern __shared__ char fsm[];
    const uint32_t smem0 = (uint32_t)__cvta_generic_to_shared(fsm);

    const int t = threadIdx.x, lane = t & 31, w = t >> 5;
    const int qb = gridDim.x - 1 - blockIdx.x;        // LPT: heavy first
    const int h = blockIdx.y, b = blockIdx.z, kvh = h >> 2;
    const int g = lane >> 3, r = lane & 7;
    const int a_row = (g & 1) * 8 + r, a_k = (g >> 1) * 8;
    const int b_row = (g >> 1) * 8 + r, b_k = (g & 1) * 8;

    const int ntiles = qb + 1;
    const size_t bS = (size_t)(b * S_);

    // stage Q tile through stage-0 K buffer
    {
        __half* s0 = (__half*)(fsm);
        const size_t qbase = (bS + qb * 64) * H_ + h * HD;
#pragma unroll
        for (int i = 0; i < 4; i++) {
            int idx = t + i * 128;
            int row = idx >> 3, c = (idx & 7) * 8;
            *(uint4*)&s0[row * ST2 + c] = *(const uint4*)(Qh + qbase + (size_t)row * H_ + c);
        }
    }
    __syncthreads();
    uint32_t qf[4][4];
#pragma unroll
    for (int ks = 0; ks < 4; ks++)
        ldsm4(qf[ks], smem0 + 2u * ((w * 16 + a_row) * ST2 + ks * 16 + a_k));
    __syncthreads();

    auto issue = [&](int kt) {
        if (kt >= ntiles) return;
        uint32_t base = smem0 + (kt & 1) * FSTAGE;
        const size_t kbK = (bS + kt * 64) * KVD + kvh * HD;
        const size_t kbV = (bS + kt * 64) * QKVD + kvh * HD;
#pragma unroll
        for (int i = 0; i < 4; i++) {
            int chunk = t + i * 128;
            int row = chunk >> 3, col = (chunk & 7) * 8;
            uint32_t so = base + (row * ST2 + col) * 2;
            cp16(so,      Kh + kbK + (size_t)row * KVD + col);
            cp16(so + FA, Vh + kbV + (size_t)row * QKVD + col);
        }
    };

    issue(0); asm volatile("cp.async.commit_group;\n");
    issue(1); asm volatile("cp.async.commit_group;\n");

    float o[8][4];
#pragma unroll
    for (int j = 0; j < 8; j++)
#pragma unroll
        for (int e = 0; e < 4; e++) o[j][e] = 0.f;
    float m0 = -3.0e38f, m1 = -3.0e38f, l0 = 0.f, l1 = 0.f;
    const int qr0 = qb * 64 + w * 16 + (lane >> 2);
    const int qr1 = qr0 + 8;

    for (int kt = 0; kt < ntiles; kt++) {
        asm volatile("cp.async.wait_group 1;\n");
        __syncthreads();

        const uint32_t base = smem0 + (kt & 1) * FSTAGE;
        const uint32_t pKh = base, pVh = base + FA;
        const int k0 = kt * 64;

        // ---- S = Q K^T ----
        float s[8][4];
#pragma unroll
        for (int j = 0; j < 8; j++)
#pragma unroll
            for (int e = 0; e < 4; e++) s[j][e] = 0.f;
#pragma unroll
        for (int ks = 0; ks < 4; ks++) {
            uint32_t bh[4][4];
#pragma unroll
            for (int nb = 0; nb < 4; nb++)
                ldsm4(bh[nb], pKh + 2u * ((nb * 16 + b_row) * ST2 + ks * 16 + b_k));
#pragma unroll
            for (int nb = 0; nb < 4; nb++)
#pragma unroll
                for (int hn = 0; hn < 2; hn++)
                    mma16816(s[nb * 2 + hn], qf[ks], bh[nb] + hn * 2);
        }

        // ---- scale + causal mask + online softmax ----
        const bool diag = (kt == ntiles - 1);
        float mx0 = -3.0e38f, mx1 = -3.0e38f;
#pragma unroll
        for (int j = 0; j < 8; j++) {
            int colb = k0 + j * 8 + (lane & 3) * 2;
#pragma unroll
            for (int e = 0; e < 4; e++) {
                float val = s[j][e] * 0.125f;
                if (diag) {
                    int col = colb + (e & 1);
                    int qr  = (e < 2) ? qr0 : qr1;
                    if (col > qr) val = -1.0e9f;
                }
                s[j][e] = val;
                if (e < 2) mx0 = fmaxf(mx0, val); else mx1 = fmaxf(mx1, val);
            }
        }
        mx0 = fmaxf(mx0, __shfl_xor_sync(0xffffffffu, mx0, 1));
        mx0 = fmaxf(mx0, __shfl_xor_sync(0xffffffffu, mx0, 2));
        mx1 = fmaxf(mx1, __shfl_xor_sync(0xffffffffu, mx1, 1));
        mx1 = fmaxf(mx1, __shfl_xor_sync(0xffffffffu, mx1, 2));
        float nm0 = fmaxf(m0, mx0), nm1 = fmaxf(m1, mx1);
        float c0 = __expf(m0 - nm0), c1 = __expf(m1 - nm1);
        l0 *= c0; l1 *= c1;
#pragma unroll
        for (int j = 0; j < 8; j++) {
            o[j][0] *= c0; o[j][1] *= c0;
            o[j][2] *= c1; o[j][3] *= c1;
        }
        m0 = nm0; m1 = nm1;
        float rs0 = 0.f, rs1 = 0.f;
#pragma unroll
        for (int j = 0; j < 8; j++) {
#pragma unroll
            for (int e = 0; e < 4; e++) {
                float p = __expf(s[j][e] - ((e < 2) ? m0 : m1));
                s[j][e] = p;
                if (e < 2) rs0 += p; else rs1 += p;
            }
        }
        l0 += rs0; l1 += rs1;

        // ---- P fragments (single fp16) ----
        uint32_t ph[4][4];
#pragma unroll
        for (int kg = 0; kg < 4; kg++)
#pragma unroll
            for (int q2 = 0; q2 < 2; q2++) {
                int j = 2 * kg + q2;
#pragma unroll
                for (int half = 0; half < 2; half++)
                    ph[kg][q2 * 2 + half] = pack_h(s[j][half * 2], s[j][half * 2 + 1]);
            }

        // ---- O += P V ----
#pragma unroll
        for (int kg = 0; kg < 4; kg++) {
            uint32_t vhf[4][4];
#pragma unroll
            for (int dt = 0; dt < 4; dt++) {
                uint32_t vaddr = 2u * ((kg * 16 + (lane & 15)) * ST2 + dt * 16 + (lane >> 4) * 8);
                ldsm4t(vhf[dt], pVh + vaddr);
            }
#pragma unroll
            for (int dt = 0; dt < 4; dt++)
#pragma unroll
                for (int hn = 0; hn < 2; hn++)
                    mma16816(o[dt * 2 + hn], ph[kg], vhf[dt] + hn * 2);
        }
        __syncthreads();
        issue(kt + 2);
        asm volatile("cp.async.commit_group;\n");
    }

    l0 += __shfl_xor_sync(0xffffffffu, l0, 1);
    l0 += __shfl_xor_sync(0xffffffffu, l0, 2);
    l1 += __shfl_xor_sync(0xffffffffu, l1, 1);
    l1 += __shfl_xor_sync(0xffffffffu, l1, 2);
    float inv0 = 1.f / l0, inv1 = 1.f / l1;
    const size_t obase = ((size_t)(b * S_) + qb * 64 + w * 16) * H_ + h * HD;
#pragma unroll
    for (int j = 0; j < 8; j++) {
        int col = j * 8 + (lane & 3) * 2;
        size_t off0 = obase + (size_t)(lane >> 2) * H_ + col;
        size_t off1 = obase + (size_t)((lane >> 2) + 8) * H_ + col;
        *(__half2*)&AOh[off0] = __floats2half2_rn(o[j][0] * inv0, o[j][1] * inv0);
        *(__half2*)&AOh[off1] = __floats2half2_rn(o[j][2] * inv1, o[j][3] * inv1);
    }
}

// ---------------------------------------------------------------------------
// inputs: x, position_ids(unused), mask(unused), wq, wk, wv, wo
// ---------------------------------------------------------------------------
extern "C" void kernel_launch(void* const* d_in, const int* in_sizes, int n_in,
                              void* d_out, int out_size) {
    const float* x  = (const float*)d_in[0];
    const float* wq = (const float*)d_in[3];
    const float* wk = (const float*)d_in[4];
    const float* wv = (const float*)d_in[5];
    const float* wo = (const float*)d_in[6];
    float* out = (float*)d_out;

    __half *qkv16, *xh, *wqkv, *woh, *aoh, *qh, *kh;
    cudaGetSymbolAddress((void**)&qkv16, g_qkv16);
    cudaGetSymbolAddress((void**)&xh,    g_xh);
    cudaGetSymbolAddress((void**)&wqkv,  g_wqkv);
    cudaGetSymbolAddress((void**)&woh,   g_woh);
    cudaGetSymbolAddress((void**)&aoh,   g_aoh);
    cudaGetSymbolAddress((void**)&qh,    g_qh);
    cudaGetSymbolAddress((void**)&kh,    g_kh);

    cudaFuncSetAttribute(gemm_pre, cudaFuncAttributeMaxDynamicSharedMemorySize, SMEMSZ);
    cudaFuncSetAttribute(flash2,   cudaFuncAttributeMaxDynamicSharedMemorySize, FSMEM);

    // single fused convert of x + all weights
    convert_all<<<(CNT + 255) / 256, 256>>>(x, wq, wk, wv, wo);

    // fused QKV projection -> fp16 packed qkv
    dim3 gqkv(QKVD / 128, MROWS / 128);    // 24 x 32 = 768 blocks
    gemm_pre<<<gqkv, 256, SMEMSZ>>>(xh, wqkv, qkv16, MROWS, QKVD, H_, 1);

    cs_table_kernel<<<(S_ * 32 + 255) / 256, 256>>>();
    int total2 = MROWS * 512 + MROWS * 128;
    rope16_kernel<<<(total2 + 255) / 256, 256>>>(qkv16);

    dim3 ga(S_ / 64, NH, B_);
    flash2<<<ga, 128, FSMEM>>>(qh, kh, qkv16 + H_ + KVD, aoh);

    // output projection -> fp32 harness buffer
    dim3 gq(H_ / 128, MROWS / 128);        // 16 x 32 = 512 blocks
    gemm_pre<<<gq, 256, SMEMSZ>>>(aoh, woh, out, MROWS, H_, H_, 0);
}

// round 17
// speedup vs baseline: 1.0981x; 1.0981x over previous
#include <cuda_runtime.h>
#include <cuda_fp16.h>
#include <math.h>
#include <stdint.h>

// Problem constants
#define B_    2
#define S_    2048
#define H_    2048
#define NH    32
#define NKV   8
#define HD    64
#define KVD   512           // NKV * HD
#define QKVD  3072          // H_ + 2*KVD
#define MROWS 4096          // B_ * S_

// fp32 scratch (fused QKV projection output)
__device__ float g_qkv[MROWS * QKVD];
__device__ float2 g_cs[S_ * 32];

// fp16 operands
__device__ __half g_xh   [MROWS * H_];
__device__ __half g_wqkv [QKVD * H_];       // wq | wk | wv packed rows
__device__ __half g_woh  [H_ * H_];
__device__ __half g_aoh  [MROWS * H_];
__device__ __half g_qh   [MROWS * H_];
__device__ __half g_kh   [MROWS * KVD];
__device__ __half g_vh   [MROWS * KVD];

// ---------------------------------------------------------------------------
// helpers
// ---------------------------------------------------------------------------
__device__ __forceinline__ void mma16816(float* c, const uint32_t* a, const uint32_t* b) {
    asm volatile(
        "mma.sync.aligned.m16n8k16.row.col.f32.f16.f16.f32 "
        "{%0,%1,%2,%3}, {%4,%5,%6,%7}, {%8,%9}, {%0,%1,%2,%3};\n"
        : "+f"(c[0]), "+f"(c[1]), "+f"(c[2]), "+f"(c[3])
        : "r"(a[0]), "r"(a[1]), "r"(a[2]), "r"(a[3]), "r"(b[0]), "r"(b[1]));
}
__device__ __forceinline__ void ldsm4(uint32_t* r, uint32_t addr) {
    asm volatile("ldmatrix.sync.aligned.m8n8.x4.shared.b16 {%0,%1,%2,%3}, [%4];\n"
                 : "=r"(r[0]), "=r"(r[1]), "=r"(r[2]), "=r"(r[3]) : "r"(addr));
}
__device__ __forceinline__ void ldsm4t(uint32_t* r, uint32_t addr) {
    asm volatile("ldmatrix.sync.aligned.m8n8.x4.trans.shared.b16 {%0,%1,%2,%3}, [%4];\n"
                 : "=r"(r[0]), "=r"(r[1]), "=r"(r[2]), "=r"(r[3]) : "r"(addr));
}
__device__ __forceinline__ uint32_t pack_h(float a, float b) {
    __half2 t = __floats2half2_rn(a, b);
    return *(uint32_t*)&t;
}
__device__ __forceinline__ void cp16(uint32_t dst, const void* src) {
    asm volatile("cp.async.cg.shared.global [%0], [%1], 16;\n" :: "r"(dst), "l"(src));
}

// ---------------------------------------------------------------------------
// Fused fp32 -> fp16 convert of x + all four weights (one launch)
// ---------------------------------------------------------------------------
#define CN0 (MROWS * H_ / 4)     // x
#define CN1 (H_ * H_ / 4)        // wq
#define CN2 (KVD * H_ / 4)       // wk
#define CN3 (KVD * H_ / 4)       // wv
#define CN4 (H_ * H_ / 4)        // wo
#define CNT (CN0 + CN1 + CN2 + CN3 + CN4)

__global__ void convert_all(const float* __restrict__ x,  const float* __restrict__ wq,
                            const float* __restrict__ wk, const float* __restrict__ wv,
                            const float* __restrict__ wo) {
    int c = blockIdx.x * blockDim.x + threadIdx.x;
    if (c >= CNT) return;
    const float* src;
    __half* dst;
    int i;
    if (c < CN0)                       { src = x;  dst = g_xh;   i = c; }
    else if (c < CN0 + CN1)            { src = wq; dst = g_wqkv; i = c - CN0; }
    else if (c < CN0 + CN1 + CN2)      { src = wk; dst = g_wqkv + (size_t)H_ * H_; i = c - CN0 - CN1; }
    else if (c < CN0 + CN1 + CN2 + CN3){ src = wv; dst = g_wqkv + (size_t)(H_ + KVD) * H_; i = c - CN0 - CN1 - CN2; }
    else                               { src = wo; dst = g_woh;  i = c - CN0 - CN1 - CN2 - CN3; }
    i *= 4;
    float4 v = *(const float4*)(src + i);
    *(__half2*)&dst[i]     = __floats2half2_rn(v.x, v.y);
    *(__half2*)&dst[i + 2] = __floats2half2_rn(v.z, v.w);
}

// ---------------------------------------------------------------------------
// Pipelined plain-fp16 GEMM: C[M,N] = A[M,K] @ B[N,K]^T
// 128x128 tile, BK=64, 3-stage cp.async, 256 threads, warp tile 64x32,
// 2 CTAs/SM (reg cap 128).
// ---------------------------------------------------------------------------
#define ST 72                      // smem row stride (fp16 elems), 64 data cols
#define ABYTES (128 * ST * 2)      // 18432 per array
#define STAGEB (2 * ABYTES)        // A, B = 36864 per stage
#define SMEMSZ (3 * STAGEB)        // 110592

__global__ void __launch_bounds__(256, 2)
gemm_pre(const __half* __restrict__ A, const __half* __restrict__ B,
         float* __restrict__ C, int M, int N, int K) {
    extern __shared__ char dsm[];
    const uint32_t smem0 = (uint32_t)__cvta_generic_to_shared(dsm);

    const int t    = threadIdx.x;
    const int lane = t & 31;
    const int w    = t >> 5;
    const int wm   = (w & 1) * 64;
    const int wn   = (w >> 1) * 32;
    const int m0   = blockIdx.y * 128;
    const int n0   = blockIdx.x * 128;

    const int g = lane >> 3, r = lane & 7;
    const int a_moff = (g & 1) * 8 + r;
    const int a_koff = (g >> 1) * 8;
    const int b_noff = (g >> 1) * 8 + r;
    const int b_koff = (g & 1) * 8;

    const int nkt = K >> 6;           // BK = 64

    auto issue = [&](int kt) {
        int k0 = kt << 6;
        uint32_t base = smem0 + (kt % 3) * STAGEB;
        // 1024 chunks of 16B per array; 4 chunks/thread each for A and B
#pragma unroll
        for (int i = 0; i < 4; i++) {
            int c = t + i * 256;
            int row = c >> 3, col = (c & 7) * 8;
            uint32_t d = base + (row * ST + col) * 2;
            cp16(d,          A + (size_t)(m0 + row) * K + k0 + col);
            cp16(d + ABYTES, B + (size_t)(n0 + row) * K + k0 + col);
        }
    };

    float acc[4][4][4];
#pragma unroll
    for (int i = 0; i < 4; i++)
#pragma unroll
        for (int j = 0; j < 4; j++)
#pragma unroll
            for (int e = 0; e < 4; e++) acc[i][j][e] = 0.f;

    issue(0); asm volatile("cp.async.commit_group;\n");
    issue(1); asm volatile("cp.async.commit_group;\n");

    for (int kt = 0; kt < nkt; kt++) {
        asm volatile("cp.async.wait_group 1;\n");
        __syncthreads();
        if (kt + 2 < nkt) issue(kt + 2);
        asm volatile("cp.async.commit_group;\n");

        const uint32_t base = smem0 + (kt % 3) * STAGEB;
        const uint32_t sA = base, sB = base + ABYTES;

#pragma unroll
        for (int ks = 0; ks < 4; ks++) {
            const int kk = ks * 16;
            uint32_t af[4][4], bf[2][4];
#pragma unroll
            for (int mi = 0; mi < 4; mi++)
                ldsm4(af[mi], sA + 2u * ((wm + mi * 16 + a_moff) * ST + kk + a_koff));
#pragma unroll
            for (int nb = 0; nb < 2; nb++)
                ldsm4(bf[nb], sB + 2u * ((wn + nb * 16 + b_noff) * ST + kk + b_koff));
#pragma unroll
            for (int mi = 0; mi < 4; mi++)
#pragma unroll
                for (int ni = 0; ni < 4; ni++)
                    mma16816(acc[mi][ni], af[mi], &bf[ni >> 1][(ni & 1) * 2]);
        }
        __syncthreads();
    }

#pragma unroll
    for (int mi = 0; mi < 4; mi++) {
        int row = m0 + wm + mi * 16 + (lane >> 2);
#pragma unroll
        for (int ni = 0; ni < 4; ni++) {
            int col = n0 + wn + ni * 8 + (lane & 3) * 2;
            *(float2*)&C[(size_t)row * N + col]       = make_float2(acc[mi][ni][0], acc[mi][ni][1]);
            *(float2*)&C[(size_t)(row + 8) * N + col] = make_float2(acc[mi][ni][2], acc[mi][ni][3]);
        }
    }
}

// ---------------------------------------------------------------------------
// cos/sin table
// ---------------------------------------------------------------------------
__global__ void cs_table_kernel() {
    int i = blockIdx.x * blockDim.x + threadIdx.x;
    if (i >= S_ * 32) return;
    int pos = i >> 5, p = i & 31;
    double inv = exp(-((double)(2 * p) / 64.0) * log(10000.0));
    double ang = (double)pos * inv;
    g_cs[i] = make_float2((float)cos(ang), (float)sin(ang));
}

// ---------------------------------------------------------------------------
// Vectorized RoPE (Q,K) + fp16 conversion from packed fp32 qkv.
// Q/K: 2 rotation pairs per thread (float2 in, half2 out). V: 4 elems/thread.
// ---------------------------------------------------------------------------
__global__ void rope_split_kernel(const float* __restrict__ qkv) {
    const int NQ2 = MROWS * 512;          // q: 1024 pairs/row, 2/thread
    const int NK2 = MROWS * 128;          // k: 256 pairs/row, 2/thread
    const int NV4 = MROWS * 128;          // v: 512 elems/row, 4/thread
    int idx = blockIdx.x * blockDim.x + threadIdx.x;
    if (idx >= NQ2 + NK2 + NV4) return;

    if (idx < NQ2 + NK2) {
        const float* srcp;
        __half* dstp;
        int row, head, pp;
        if (idx < NQ2) {
            row = idx >> 9; int rem = idx & 511;
            head = rem >> 4; pp = (rem & 15) * 2;
            srcp = qkv + (size_t)row * QKVD + head * HD;
            dstp = g_qh + (size_t)row * H_ + head * HD;
        } else {
            int i2 = idx - NQ2;
            row = i2 >> 7; int rem = i2 & 127;
            head = rem >> 4; pp = (rem & 15) * 2;
            srcp = qkv + (size_t)row * QKVD + H_ + head * HD;
            dstp = g_kh + (size_t)row * KVD + head * HD;
        }
        int pos = row & (S_ - 1);
        float2 csA = g_cs[pos * 32 + pp];
        float2 csB = g_cs[pos * 32 + pp + 1];
        float2 v0 = *(const float2*)(srcp + pp);        // x[pp], x[pp+1]
        float2 v1 = *(const float2*)(srcp + pp + 32);   // x[pp+32], x[pp+33]
        *(__half2*)(dstp + pp) = __floats2half2_rn(
            v0.x * csA.x - v1.x * csA.y, v0.y * csB.x - v1.y * csB.y);
        *(__half2*)(dstp + pp + 32) = __floats2half2_rn(
            v1.x * csA.x + v0.x * csA.y, v1.y * csB.x + v0.y * csB.y);
    } else {
        int i2 = idx - NQ2 - NK2;
        int row = i2 >> 7;
        int e = (i2 & 127) * 4;
        const float* srcp = qkv + (size_t)row * QKVD + H_ + KVD + e;
        __half* dstp = g_vh + (size_t)row * KVD + e;
        float4 v = *(const float4*)srcp;
        *(__half2*)dstp       = __floats2half2_rn(v.x, v.y);
        *(__half2*)(dstp + 2) = __floats2half2_rn(v.z, v.w);
    }
}

// ---------------------------------------------------------------------------
// Tensor-core causal flash attention: all single fp16 (1-pass QK, 1-pass PV).
// 2-stage cp.async; LPT block order.
// ---------------------------------------------------------------------------
#define ST2 72
#define FA  (64 * ST2 * 2)
#define FSTAGE (2 * FA)             // Kh, Vh
#define FSMEM  (2 * FSTAGE)         // 36864

__global__ void __launch_bounds__(128)
flash2(const __half* __restrict__ Qh,
       const __half* __restrict__ Kh, const __half* __restrict__ Vh,
       __half* __restrict__ AOh) {
    extern __shared__ char fsm[];
    const uint32_t smem0 = (uint32_t)__cvta_generic_to_shared(fsm);

    const int t = threadIdx.x, lane = t & 31, w = t >> 5;
    const int qb = gridDim.x - 1 - blockIdx.x;        // LPT: heavy first
    const int h = blockIdx.y, b = blockIdx.z, kvh = h >> 2;
    const int g = lane >> 3, r = lane & 7;
    const int a_row = (g & 1) * 8 + r, a_k = (g >> 1) * 8;
    const int b_row = (g >> 1) * 8 + r, b_k = (g & 1) * 8;

    const int ntiles = qb + 1;
    const size_t bS = (size_t)(b * S_);

    // stage Q tile through stage-0 Kh buffer
    {
        __half* s0 = (__half*)(fsm);
        const size_t qbase = (bS + qb * 64) * H_ + h * HD;
#pragma unroll
        for (int i = 0; i < 4; i++) {
            int idx = t + i * 128;
            int row = idx >> 3, c = (idx & 7) * 8;
            *(uint4*)&s0[row * ST2 + c] = *(const uint4*)(Qh + qbase + (size_t)row * H_ + c);
        }
    }
    __syncthreads();
    uint32_t qf[4][4];
#pragma unroll
    for (int ks = 0; ks < 4; ks++)
        ldsm4(qf[ks], smem0 + 2u * ((w * 16 + a_row) * ST2 + ks * 16 + a_k));
    __syncthreads();

    auto issue = [&](int kt) {
        if (kt >= ntiles) return;
        uint32_t base = smem0 + (kt & 1) * FSTAGE;
        const size_t kb = (bS + kt * 64) * KVD + kvh * HD;
#pragma unroll
        for (int i = 0; i < 4; i++) {
            int chunk = t + i * 128;
            int row = chunk >> 3, col = (chunk & 7) * 8;
            size_t go = kb + (size_t)row * KVD + col;
            uint32_t so = base + (row * ST2 + col) * 2;
            cp16(so,      Kh + go);
            cp16(so + FA, Vh + go);
        }
    };

    issue(0); asm volatile("cp.async.commit_group;\n");
    issue(1); asm volatile("cp.async.commit_group;\n");

    float o[8][4];
#pragma unroll
    for (int j = 0; j < 8; j++)
#pragma unroll
        for (int e = 0; e < 4; e++) o[j][e] = 0.f;
    float m0 = -3.0e38f, m1 = -3.0e38f, l0 = 0.f, l1 = 0.f;
    const int qr0 = qb * 64 + w * 16 + (lane >> 2);
    const int qr1 = qr0 + 8;

    for (int kt = 0; kt < ntiles; kt++) {
        asm volatile("cp.async.wait_group 1;\n");
        __syncthreads();

        const uint32_t base = smem0 + (kt & 1) * FSTAGE;
        const uint32_t pKh = base, pVh = base + FA;
        const int k0 = kt * 64;

        // ---- S = Q K^T ----
        float s[8][4];
#pragma unroll
        for (int j = 0; j < 8; j++)
#pragma unroll
            for (int e = 0; e < 4; e++) s[j][e] = 0.f;
#pragma unroll
        for (int ks = 0; ks < 4; ks++) {
            uint32_t bh[4][4];
#pragma unroll
            for (int nb = 0; nb < 4; nb++)
                ldsm4(bh[nb], pKh + 2u * ((nb * 16 + b_row) * ST2 + ks * 16 + b_k));
#pragma unroll
            for (int nb = 0; nb < 4; nb++)
#pragma unroll
                for (int hn = 0; hn < 2; hn++)
                    mma16816(s[nb * 2 + hn], qf[ks], bh[nb] + hn * 2);
        }

        // ---- scale + causal mask + online softmax ----
        const bool diag = (kt == ntiles - 1);
        float mx0 = -3.0e38f, mx1 = -3.0e38f;
#pragma unroll
        for (int j = 0; j < 8; j++) {
            int colb = k0 + j * 8 + (lane & 3) * 2;
#pragma unroll
            for (int e = 0; e < 4; e++) {
                float val = s[j][e] * 0.125f;
                if (diag) {
                    int col = colb + (e & 1);
                    int qr  = (e < 2) ? qr0 : qr1;
                    if (col > qr) val = -1.0e9f;
                }
                s[j][e] = val;
                if (e < 2) mx0 = fmaxf(mx0, val); else mx1 = fmaxf(mx1, val);
            }
        }
        mx0 = fmaxf(mx0, __shfl_xor_sync(0xffffffffu, mx0, 1));
        mx0 = fmaxf(mx0, __shfl_xor_sync(0xffffffffu, mx0, 2));
        mx1 = fmaxf(mx1, __shfl_xor_sync(0xffffffffu, mx1, 1));
        mx1 = fmaxf(mx1, __shfl_xor_sync(0xffffffffu, mx1, 2));
        float nm0 = fmaxf(m0, mx0), nm1 = fmaxf(m1, mx1);
        float c0 = __expf(m0 - nm0), c1 = __expf(m1 - nm1);
        l0 *= c0; l1 *= c1;
#pragma unroll
        for (int j = 0; j < 8; j++) {
            o[j][0] *= c0; o[j][1] *= c0;
            o[j][2] *= c1; o[j][3] *= c1;
        }
        m0 = nm0; m1 = nm1;
        float rs0 = 0.f, rs1 = 0.f;
#pragma unroll
        for (int j = 0; j < 8; j++) {
#pragma unroll
            for (int e = 0; e < 4; e++) {
                float p = __expf(s[j][e] - ((e < 2) ? m0 : m1));
                s[j][e] = p;
                if (e < 2) rs0 += p; else rs1 += p;
            }
        }
        l0 += rs0; l1 += rs1;

        // ---- P fragments (single fp16) ----
        uint32_t ph[4][4];
#pragma unroll
        for (int kg = 0; kg < 4; kg++)
#pragma unroll
            for (int q2 = 0; q2 < 2; q2++) {
                int j = 2 * kg + q2;
#pragma unroll
                for (int half = 0; half < 2; half++)
                    ph[kg][q2 * 2 + half] = pack_h(s[j][half * 2], s[j][half * 2 + 1]);
            }

        // ---- O += P V ----
#pragma unroll
        for (int kg = 0; kg < 4; kg++) {
            uint32_t vhf[4][4];
#pragma unroll
            for (int dt = 0; dt < 4; dt++) {
                uint32_t vaddr = 2u * ((kg * 16 + (lane & 15)) * ST2 + dt * 16 + (lane >> 4) * 8);
                ldsm4t(vhf[dt], pVh + vaddr);
            }
#pragma unroll
            for (int dt = 0; dt < 4; dt++)
#pragma unroll
                for (int hn = 0; hn < 2; hn++)
                    mma16816(o[dt * 2 + hn], ph[kg], vhf[dt] + hn * 2);
        }
        __syncthreads();
        issue(kt + 2);
        asm volatile("cp.async.commit_group;\n");
    }

    l0 += __shfl_xor_sync(0xffffffffu, l0, 1);
    l0 += __shfl_xor_sync(0xffffffffu, l0, 2);
    l1 += __shfl_xor_sync(0xffffffffu, l1, 1);
    l1 += __shfl_xor_sync(0xffffffffu, l1, 2);
    float inv0 = 1.f / l0, inv1 = 1.f / l1;
    const size_t obase = ((size_t)(b * S_) + qb * 64 + w * 16) * H_ + h * HD;
#pragma unroll
    for (int j = 0; j < 8; j++) {
        int col = j * 8 + (lane & 3) * 2;
        size_t off0 = obase + (size_t)(lane >> 2) * H_ + col;
        size_t off1 = obase + (size_t)((lane >> 2) + 8) * H_ + col;
        *(__half2*)&AOh[off0] = __floats2half2_rn(o[j][0] * inv0, o[j][1] * inv0);
        *(__half2*)&AOh[off1] = __floats2half2_rn(o[j][2] * inv1, o[j][3] * inv1);
    }
}

// ---------------------------------------------------------------------------
// inputs: x, position_ids(unused), mask(unused), wq, wk, wv, wo
// ---------------------------------------------------------------------------
extern "C" void kernel_launch(void* const* d_in, const int* in_sizes, int n_in,
                              void* d_out, int out_size) {
    const float* x  = (const float*)d_in[0];
    const float* wq = (const float*)d_in[3];
    const float* wk = (const float*)d_in[4];
    const float* wv = (const float*)d_in[5];
    const float* wo = (const float*)d_in[6];
    float* out = (float*)d_out;

    float* qkv;
    cudaGetSymbolAddress((void**)&qkv, g_qkv);
    __half *xh, *wqkv, *woh, *aoh, *qh, *kh, *vh;
    cudaGetSymbolAddress((void**)&xh,   g_xh);
    cudaGetSymbolAddress((void**)&wqkv, g_wqkv);
    cudaGetSymbolAddress((void**)&woh,  g_woh);
    cudaGetSymbolAddress((void**)&aoh,  g_aoh);
    cudaGetSymbolAddress((void**)&qh,   g_qh);
    cudaGetSymbolAddress((void**)&kh,   g_kh);
    cudaGetSymbolAddress((void**)&vh,   g_vh);

    cudaFuncSetAttribute(gemm_pre, cudaFuncAttributeMaxDynamicSharedMemorySize, SMEMSZ);
    cudaFuncSetAttribute(flash2,   cudaFuncAttributeMaxDynamicSharedMemorySize, FSMEM);

    // single fused convert of x + all weights
    convert_all<<<(CNT + 255) / 256, 256>>>(x, wq, wk, wv, wo);

    // fused QKV projection: one GEMM, N = 3072
    dim3 gqkv(QKVD / 128, MROWS / 128);    // 24 x 32 = 768 blocks
    gemm_pre<<<gqkv, 256, SMEMSZ>>>(xh, wqkv, qkv, MROWS, QKVD, H_);

    cs_table_kernel<<<(S_ * 32 + 255) / 256, 256>>>();
    int total = MROWS * 512 + MROWS * 128 + MROWS * 128;
    rope_split_kernel<<<(total + 255) / 256, 256>>>(qkv);

    dim3 ga(S_ / 64, NH, B_);
    flash2<<<ga, 128, FSMEM>>>(qh, kh, vh, aoh);

    // output projection
    dim3 gq(H_ / 128, MROWS / 128);        // 16 x 32 = 512 blocks
    gemm_pre<<<gq, 256, SMEMSZ>>>(aoh, woh, out, MROWS, H_, H_);
}